// round 7
// baseline (speedup 1.0000x reference)
#include <cuda_runtime.h>
#include <cstdint>
#include <math_constants.h>

// PolyLoss: N=4096 rows, V=128 circular shifts, last dim = 2 (packed f32x2).
// per_shift[n,s] = (1/V) sum_v |pred[n,(s+v)%V] - gt[n,v]|_1 ; loss = mean_n min_s
//
// 4 rows per 256-thread CTA, 2 warps per row (warp parity vh = v-half).
// Within a warp: t=lane&15 owns shifts 8t..8t+7, hh=lane>>4 owns a 32-v
// sub-half. 8-iter mainloop, 128 ACC instrs per 4 LDS.128 (~9% overhead).
// Quadrant sums combined via shfl_xor(16) then one smem add across warps.

#define NROWS 4096
#define V 128
#define RPC 4
#define NCTA (NROWS / RPC)    // 1024
#define THREADS 256

__device__ float g_partial[NCTA];
__device__ int g_ctr;

__device__ __forceinline__ uint64_t fma2(uint64_t a, uint64_t b, uint64_t c) {
    uint64_t d;
    asm("fma.rn.f32x2 %0, %1, %2, %3;" : "=l"(d) : "l"(a), "l"(b), "l"(c));
    return d;
}

// acc += | p - g | (componentwise, packed): FFMA2 + 2xLOP3 + FFMA2
#define ACC(p2, g2, acc) do {                      \
    uint64_t _d = fma2((g2), NEG1, (p2));          \
    _d &= 0x7fffffff7fffffffULL;                   \
    (acc) = fma2(_d, ONE1, (acc));                 \
} while (0)

__global__ void __launch_bounds__(THREADS, 4) polyloss_kernel(
    const float* __restrict__ pred, const float* __restrict__ gt,
    float* __restrict__ out)
{
    // Entry e_k = (pos 2k, pos 2k+1), k=0..63 circular. Even entries in sA,
    // odd in sB, duplicated (sX[j]=sX[j+32]); index 64 pads e_0/e_1.
    __shared__ ulonglong2 sA[RPC][66];
    __shared__ ulonglong2 sB[RPC][66];
    __shared__ ulonglong2 sg[RPC][64];
    __shared__ float4 ssumA[2 * RPC][16];
    __shared__ float4 ssumB[2 * RPC][16];
    __shared__ float s_rowmin[RPC];
    __shared__ int s_is_last;
    __shared__ float s_red[THREADS];

    const int tid  = threadIdx.x;
    const int w    = tid >> 5;          // 0..7
    const int lane = tid & 31;
    const int rl   = w >> 1;            // row within CTA
    const int vh   = w & 1;             // warp's v-half (64 v's)
    const int t    = lane & 15;         // shifts 8t..8t+7
    const int hh   = lane >> 4;         // 32-v sub-half within warp's half

    const uint64_t NEG1 = 0xBF800000BF800000ULL;
    const uint64_t ONE1 = 0x3F8000003F800000ULL;

    // ---- stage 4 rows, 64 threads each (threads 64r..64r+63 = warps 2r,2r+1
    //      stage row r, which exactly those warps consume) ----
    {
        const int rr = tid >> 6;
        const int i  = tid & 63;
        const ulonglong2* prow =
            reinterpret_cast<const ulonglong2*>(pred) + (blockIdx.x * RPC + rr) * 64;
        const ulonglong2* grow =
            reinterpret_cast<const ulonglong2*>(gt)   + (blockIdx.x * RPC + rr) * 64;
        ulonglong2 e = prow[i];
        const int j = i >> 1;
        if (i & 1) { sB[rr][j] = e; sB[rr][j + 32] = e; }
        else       { sA[rr][j] = e; sA[rr][j + 32] = e; }
        if (i == 0) sA[rr][64] = e;   // pad = e_0
        if (i == 1) sB[rr][64] = e;   // pad = e_1
        sg[rr][i] = grow[i];
    }
    // 64-thread named barrier per row group (ids 1..4), uniform per group
    asm volatile("bar.sync %0, 64;" :: "r"(1 + rl) : "memory");

    // ---- mainloop: 8 blocks x 4 v's. Window entries j0+m..j0+m+2 (12
    //      positions) cover shifts 8t..8t+7 x v-offsets 0..3 ----
    uint64_t a0 = 0, a1 = 0, a2 = 0, a3 = 0, a4 = 0, a5 = 0, a6 = 0, a7 = 0;
    const int j0 = 2 * t + 16 * vh + 8 * hh;
    const ulonglong2* Ap = sA[rl];
    const ulonglong2* Bp = sB[rl];
    const ulonglong2* gp = sg[rl] + 32 * vh + 16 * hh;

    ulonglong2 Pa = Ap[j0];      // rel positions 0,1
    ulonglong2 Pb = Bp[j0];      // 2,3
    ulonglong2 Pc = Ap[j0 + 1];  // 4,5
    ulonglong2 Pd = Bp[j0 + 1];  // 6,7
    ulonglong2 Pe = Ap[j0 + 2];  // 8,9
    ulonglong2 Pf = Bp[j0 + 2];  // 10,11

    #pragma unroll
    for (int m = 0; m < 8; m++) {
        ulonglong2 G0 = gp[2 * m];       // gt[v0], gt[v0+1]
        ulonglong2 G1 = gp[2 * m + 1];   // gt[v0+2], gt[v0+3]
        // u=0: rel positions r+0, r=0..7
        ACC(Pa.x, G0.x, a0); ACC(Pa.y, G0.x, a1); ACC(Pb.x, G0.x, a2); ACC(Pb.y, G0.x, a3);
        ACC(Pc.x, G0.x, a4); ACC(Pc.y, G0.x, a5); ACC(Pd.x, G0.x, a6); ACC(Pd.y, G0.x, a7);
        // u=1: r+1
        ACC(Pa.y, G0.y, a0); ACC(Pb.x, G0.y, a1); ACC(Pb.y, G0.y, a2); ACC(Pc.x, G0.y, a3);
        ACC(Pc.y, G0.y, a4); ACC(Pd.x, G0.y, a5); ACC(Pd.y, G0.y, a6); ACC(Pe.x, G0.y, a7);
        // u=2: r+2
        ACC(Pb.x, G1.x, a0); ACC(Pb.y, G1.x, a1); ACC(Pc.x, G1.x, a2); ACC(Pc.y, G1.x, a3);
        ACC(Pd.x, G1.x, a4); ACC(Pd.y, G1.x, a5); ACC(Pe.x, G1.x, a6); ACC(Pe.y, G1.x, a7);
        // u=3: r+3
        ACC(Pb.y, G1.y, a0); ACC(Pc.x, G1.y, a1); ACC(Pc.y, G1.y, a2); ACC(Pd.x, G1.y, a3);
        ACC(Pd.y, G1.y, a4); ACC(Pe.x, G1.y, a5); ACC(Pe.y, G1.y, a6); ACC(Pf.x, G1.y, a7);
        // slide by 1 index (4 positions); full unroll -> register renames
        Pa = Pc; Pb = Pd; Pc = Pe; Pd = Pf;
        Pe = Ap[j0 + m + 3];
        Pf = Bp[j0 + m + 3];
    }

    // ---- fold packed halves; combine hh sub-halves via shfl ----
    float s0 = __uint_as_float((uint32_t)a0) + __uint_as_float((uint32_t)(a0 >> 32));
    float s1 = __uint_as_float((uint32_t)a1) + __uint_as_float((uint32_t)(a1 >> 32));
    float s2 = __uint_as_float((uint32_t)a2) + __uint_as_float((uint32_t)(a2 >> 32));
    float s3 = __uint_as_float((uint32_t)a3) + __uint_as_float((uint32_t)(a3 >> 32));
    float s4 = __uint_as_float((uint32_t)a4) + __uint_as_float((uint32_t)(a4 >> 32));
    float s5 = __uint_as_float((uint32_t)a5) + __uint_as_float((uint32_t)(a5 >> 32));
    float s6 = __uint_as_float((uint32_t)a6) + __uint_as_float((uint32_t)(a6 >> 32));
    float s7 = __uint_as_float((uint32_t)a7) + __uint_as_float((uint32_t)(a7 >> 32));
    s0 += __shfl_xor_sync(0xffffffffu, s0, 16);
    s1 += __shfl_xor_sync(0xffffffffu, s1, 16);
    s2 += __shfl_xor_sync(0xffffffffu, s2, 16);
    s3 += __shfl_xor_sync(0xffffffffu, s3, 16);
    s4 += __shfl_xor_sync(0xffffffffu, s4, 16);
    s5 += __shfl_xor_sync(0xffffffffu, s5, 16);
    s6 += __shfl_xor_sync(0xffffffffu, s6, 16);
    s7 += __shfl_xor_sync(0xffffffffu, s7, 16);
    if (lane < 16) {
        ssumA[w][t] = make_float4(s0, s1, s2, s3);
        ssumB[w][t] = make_float4(s4, s5, s6, s7);
    }
    __syncthreads();

    // ---- combine v-halves + row min: warp r handles row r ----
    if (w < RPC) {
        float mn = CUDART_INF_F;
        if (lane < 16) {
            float4 xa = ssumA[2 * w][lane], ya = ssumA[2 * w + 1][lane];
            float4 xb = ssumB[2 * w][lane], yb = ssumB[2 * w + 1][lane];
            float t0 = xa.x + ya.x, t1 = xa.y + ya.y;
            float t2 = xa.z + ya.z, t3 = xa.w + ya.w;
            float t4 = xb.x + yb.x, t5 = xb.y + yb.y;
            float t6 = xb.z + yb.z, t7 = xb.w + yb.w;
            mn = fminf(fminf(fminf(t0, t1), fminf(t2, t3)),
                       fminf(fminf(t4, t5), fminf(t6, t7)));
        }
        #pragma unroll
        for (int off = 8; off > 0; off >>= 1)
            mn = fminf(mn, __shfl_xor_sync(0xffffffffu, mn, off));
        if (lane == 0) s_rowmin[w] = mn;
    }
    __syncthreads();

    // ---- CTA partial + last-CTA ticket reduction ----
    if (tid == 0) {
        g_partial[blockIdx.x] =
            (s_rowmin[0] + s_rowmin[1]) + (s_rowmin[2] + s_rowmin[3]);
        __threadfence();
        int ticket = atomicAdd(&g_ctr, 1);
        s_is_last = (ticket == NCTA - 1);
    }
    __syncthreads();

    if (s_is_last) {
        __threadfence();
        float acc = 0.f;
        #pragma unroll
        for (int i = tid; i < NCTA; i += THREADS)
            acc += g_partial[i];
        s_red[tid] = acc;
        __syncthreads();
        #pragma unroll
        for (int off = THREADS / 2; off > 0; off >>= 1) {
            if (tid < off) s_red[tid] += s_red[tid + off];
            __syncthreads();
        }
        if (tid == 0) {
            out[0] = s_red[0] * (1.0f / ((float)NROWS * (float)V));
            g_ctr = 0;  // reset for next graph replay
        }
    }
}

extern "C" void kernel_launch(void* const* d_in, const int* in_sizes, int n_in,
                              void* d_out, int out_size)
{
    const float* pred = (const float*)d_in[0];
    const float* gt   = (const float*)d_in[1];
    polyloss_kernel<<<NCTA, THREADS>>>(pred, gt, (float*)d_out);
}